// round 8
// baseline (speedup 1.0000x reference)
#include <cuda_runtime.h>
#include <cuda_fp16.h>
#include <cstdint>

// ============================================================================
// BinaryLinear: out[m,n] = sum_k x[m,k]*sign(W[n,k]) + bias[n]
// M = 4096 (2x2048), N = 4096, K = 4096, fp32 in/out.
//
// ptxas for this harness targets compute_103 (no 'a') -> tcgen05 unavailable.
// Use mma.sync.m16n8k16 (HMMA) with fp16 operands, fp32 accum.
// sign(W) in {-1,0,+1} is exact in fp16. Split x = x_hi + x_lo (fp16 pair)
// and accumulate BOTH products into the same fp32 accumulators, sharing B
// fragments. 4-stage cp.async pipeline.
// ============================================================================

#define MTOT 4096
#define NTOT 4096
#define KTOT 4096
#define BM 128
#define BN 256
#define BK 32            // k elements per stage
#define NKT (KTOT / BK)  // 128 k-tiles
#define THREADS 256      // 8 warps: 2 (m) x 4 (n), warp tile 64x64

// SMEM: per stage, rows padded to 80B (64B data + 16B pad) -> conflict-free
// frag loads and 16B-aligned cp.async.
//   A_hi: 128 rows x 80B = 10240
//   A_lo: 128 rows x 80B = 10240
//   B   : 256 rows x 80B = 20480
#define ROW_PITCH 80
#define OFF_ALO 10240
#define OFF_B   20480
#define STAGE_BYTES 40960
#define NSTAGE 4
#define SMEM_BIAS (NSTAGE * STAGE_BYTES)          // 163840
#define SMEM_TOTAL (SMEM_BIAS + BN * 4)           // 164864

// --- scratch (no cudaMalloc allowed) ---
__device__ __half g_xhi[(size_t)MTOT * KTOT];
__device__ __half g_xlo[(size_t)MTOT * KTOT];
__device__ __half g_ws [(size_t)NTOT * KTOT];

// ============================================================================
// helpers
// ============================================================================
__device__ __forceinline__ uint32_t smem_u32(const void* p) {
    uint32_t a;
    asm("{ .reg .u64 t; cvta.to.shared.u64 t, %1; cvt.u32.u64 %0, t; }"
        : "=r"(a) : "l"(p));
    return a;
}

#define CP_ASYNC16(dst_smem, src_gptr) \
    asm volatile("cp.async.cg.shared.global [%0], [%1], 16;" \
        :: "r"((uint32_t)(dst_smem)), "l"(src_gptr) : "memory")
#define CP_ASYNC_COMMIT() asm volatile("cp.async.commit_group;" ::: "memory")
#define CP_ASYNC_WAIT_2() asm volatile("cp.async.wait_group 2;" ::: "memory")

__device__ __forceinline__ uint32_t lds32(uint32_t a) {
    uint32_t v;
    asm volatile("ld.shared.b32 %0, [%1];" : "=r"(v) : "r"(a));
    return v;
}

#define MMA16816(d, a0, a1, a2, a3, b0, b1) \
    asm volatile( \
        "mma.sync.aligned.m16n8k16.row.col.f32.f16.f16.f32 " \
        "{%0,%1,%2,%3}, {%4,%5,%6,%7}, {%8,%9}, {%0,%1,%2,%3};" \
        : "+f"((d)[0]), "+f"((d)[1]), "+f"((d)[2]), "+f"((d)[3]) \
        : "r"(a0), "r"(a1), "r"(a2), "r"(a3), "r"(b0), "r"(b1))

// ============================================================================
// Prep kernels: x -> (hi, lo) fp16 pair; W -> sign in fp16
// ============================================================================
__global__ void prep_x_kernel(const float4* __restrict__ x) {
    size_t i = (size_t)blockIdx.x * blockDim.x + threadIdx.x;
    if (i >= (size_t)MTOT * KTOT / 4) return;
    float4 v = x[i];
    __half h0 = __float2half_rn(v.x);
    __half h1 = __float2half_rn(v.y);
    __half h2 = __float2half_rn(v.z);
    __half h3 = __float2half_rn(v.w);
    __half l0 = __float2half_rn(v.x - __half2float(h0));
    __half l1 = __float2half_rn(v.y - __half2float(h1));
    __half l2 = __float2half_rn(v.z - __half2float(h2));
    __half l3 = __float2half_rn(v.w - __half2float(h3));
    __half2* xh = reinterpret_cast<__half2*>(g_xhi);
    __half2* xl = reinterpret_cast<__half2*>(g_xlo);
    xh[2 * i]     = __halves2half2(h0, h1);
    xh[2 * i + 1] = __halves2half2(h2, h3);
    xl[2 * i]     = __halves2half2(l0, l1);
    xl[2 * i + 1] = __halves2half2(l2, l3);
}

__global__ void prep_w_kernel(const float4* __restrict__ w) {
    size_t i = (size_t)blockIdx.x * blockDim.x + threadIdx.x;
    if (i >= (size_t)NTOT * KTOT / 4) return;
    float4 v = w[i];
    float s0 = (v.x > 0.f) ? 1.f : ((v.x < 0.f) ? -1.f : 0.f);
    float s1 = (v.y > 0.f) ? 1.f : ((v.y < 0.f) ? -1.f : 0.f);
    float s2 = (v.z > 0.f) ? 1.f : ((v.z < 0.f) ? -1.f : 0.f);
    float s3 = (v.w > 0.f) ? 1.f : ((v.w < 0.f) ? -1.f : 0.f);
    __half2* ws = reinterpret_cast<__half2*>(g_ws);
    ws[2 * i]     = __halves2half2(__float2half_rn(s0), __float2half_rn(s1));
    ws[2 * i + 1] = __halves2half2(__float2half_rn(s2), __float2half_rn(s3));
}

// ============================================================================
// GEMM: CTA 128x256, warp tile 64x64, BK=32, 4-stage cp.async pipeline.
// Per k16 step: load B frags once; mma with A_hi frags, then A_lo frags
// (A frag registers reused), all into the same fp32 accumulators.
// ============================================================================
__global__ void __launch_bounds__(THREADS, 1)
bgemm_kernel(const float* __restrict__ bias, float* __restrict__ out) {
    extern __shared__ char smem[];
    const uint32_t sb = smem_u32(smem);
    const int tid  = threadIdx.x;
    const int lane = tid & 31;
    const int wid  = tid >> 5;         // 0..7
    const int wm   = wid >> 2;         // 0..1  (m group of 64 rows)
    const int wn   = wid & 3;          // 0..3  (n group of 64 cols)
    const int m0 = blockIdx.y * BM;
    const int n0 = blockIdx.x * BN;

    // Stage bias (BN == THREADS)
    reinterpret_cast<float*>(smem + SMEM_BIAS)[tid] = bias[n0 + tid];

    const char* xhi_b = reinterpret_cast<const char*>(g_xhi);
    const char* xlo_b = reinterpret_cast<const char*>(g_xlo);
    const char* ws_b  = reinterpret_cast<const char*>(g_ws);

    // ---- loader: stage k-tile kt into stage buffer s ----
    auto issue_loads = [&](int s, int kt) {
        const uint32_t sbase = sb + s * STAGE_BYTES;
        const size_t kbyte = (size_t)kt * (BK * 2);   // 64 bytes into each row
        // A_hi / A_lo: 128 rows x 4 chunks -> 512 chunks, 2 per thread each
        #pragma unroll
        for (int it = 0; it < 2; ++it) {
            int idx = tid + it * THREADS;
            int r = idx >> 2, c = idx & 3;
            uint32_t d = (uint32_t)(r * ROW_PITCH + c * 16);
            size_t g = (((size_t)(m0 + r)) << 13) + kbyte + (c << 4);
            CP_ASYNC16(sbase + d, xhi_b + g);
            CP_ASYNC16(sbase + OFF_ALO + d, xlo_b + g);
        }
        // B: 256 rows x 4 chunks -> 1024 chunks, 4 per thread
        #pragma unroll
        for (int it = 0; it < 4; ++it) {
            int idx = tid + it * THREADS;
            int r = idx >> 2, c = idx & 3;
            uint32_t d = (uint32_t)(r * ROW_PITCH + c * 16);
            CP_ASYNC16(sbase + OFF_B + d,
                       ws_b + (((size_t)(n0 + r)) << 13) + kbyte + (c << 4));
        }
    };

    // Prologue: stage kt = 0, 1, 2 (groups G0, G1, G2)
    issue_loads(0, 0);
    CP_ASYNC_COMMIT();
    issue_loads(1, 1);
    CP_ASYNC_COMMIT();
    issue_loads(2, 2);
    CP_ASYNC_COMMIT();

    float acc[4][8][4];
    #pragma unroll
    for (int i = 0; i < 4; ++i)
        #pragma unroll
        for (int j = 0; j < 8; ++j)
            #pragma unroll
            for (int k = 0; k < 4; ++k) acc[i][j][k] = 0.f;

    // Per-lane fragment address components
    const int qrow = lane >> 2;          // 0..7
    const int qcol = (lane & 3) << 2;    // byte offset of k half-pair

    for (int kt = 0; kt < NKT; ++kt) {
        // Groups pending after this: G(kt+1), G(kt+2) -> loads(kt) complete.
        CP_ASYNC_WAIT_2();
        __syncthreads();        // all warps done computing kt-1

        // Prefetch kt+3 into buffer (kt+3)%4 == (kt-1)%4 (safe: sync above)
        if (kt + 3 < NKT) issue_loads((kt + 3) % NSTAGE, kt + 3);
        CP_ASYNC_COMMIT();      // empty group at tail keeps numbering uniform

        const uint32_t sA  = sb + (kt % NSTAGE) * STAGE_BYTES;
        const uint32_t sAl = sA + OFF_ALO;
        const uint32_t sBb = sA + OFF_B;

        #pragma unroll
        for (int ks = 0; ks < 2; ++ks) {
            const uint32_t kofs = ks * 32 + qcol;   // bytes within row
            // B fragments: 8 n8-frags, 2 regs each (shared by hi & lo passes)
            uint32_t b[8][2];
            #pragma unroll
            for (int nf = 0; nf < 8; ++nf) {
                uint32_t addr = sBb + (uint32_t)((wn * 64 + nf * 8 + qrow) * ROW_PITCH) + kofs;
                b[nf][0] = lds32(addr);
                b[nf][1] = lds32(addr + 16);        // k+8
            }
            // --- pass 1: A_hi ---
            uint32_t a[4][4];
            #pragma unroll
            for (int mf = 0; mf < 4; ++mf) {
                uint32_t addr = sA + (uint32_t)((wm * 64 + mf * 16 + qrow) * ROW_PITCH) + kofs;
                a[mf][0] = lds32(addr);
                a[mf][1] = lds32(addr + 8 * ROW_PITCH);      // row+8
                a[mf][2] = lds32(addr + 16);                 // k+8
                a[mf][3] = lds32(addr + 8 * ROW_PITCH + 16);
            }
            #pragma unroll
            for (int mf = 0; mf < 4; ++mf)
                #pragma unroll
                for (int nf = 0; nf < 8; ++nf)
                    MMA16816(acc[mf][nf], a[mf][0], a[mf][1], a[mf][2], a[mf][3],
                             b[nf][0], b[nf][1]);
            // --- pass 2: A_lo (reuse a regs) ---
            #pragma unroll
            for (int mf = 0; mf < 4; ++mf) {
                uint32_t addr = sAl + (uint32_t)((wm * 64 + mf * 16 + qrow) * ROW_PITCH) + kofs;
                a[mf][0] = lds32(addr);
                a[mf][1] = lds32(addr + 8 * ROW_PITCH);
                a[mf][2] = lds32(addr + 16);
                a[mf][3] = lds32(addr + 8 * ROW_PITCH + 16);
            }
            #pragma unroll
            for (int mf = 0; mf < 4; ++mf)
                #pragma unroll
                for (int nf = 0; nf < 8; ++nf)
                    MMA16816(acc[mf][nf], a[mf][0], a[mf][1], a[mf][2], a[mf][3],
                             b[nf][0], b[nf][1]);
        }
    }

    // Epilogue: add bias, write fp32
    const float* bs = reinterpret_cast<const float*>(smem + SMEM_BIAS);
    #pragma unroll
    for (int mf = 0; mf < 4; ++mf) {
        const int row = m0 + wm * 64 + mf * 16 + qrow;
        #pragma unroll
        for (int nf = 0; nf < 8; ++nf) {
            const int lc = wn * 64 + nf * 8 + ((lane & 3) << 1);
            const float b0 = bs[lc], b1 = bs[lc + 1];
            float2 v0 = make_float2(acc[mf][nf][0] + b0, acc[mf][nf][1] + b1);
            float2 v1 = make_float2(acc[mf][nf][2] + b0, acc[mf][nf][3] + b1);
            *reinterpret_cast<float2*>(out + (size_t)row * NTOT + n0 + lc) = v0;
            *reinterpret_cast<float2*>(out + (size_t)(row + 8) * NTOT + n0 + lc) = v1;
        }
    }
}

// ============================================================================
// Launch
// ============================================================================
extern "C" void kernel_launch(void* const* d_in, const int* in_sizes, int n_in,
                              void* d_out, int out_size) {
    (void)in_sizes; (void)n_in; (void)out_size;
    const float* x    = reinterpret_cast<const float*>(d_in[0]);
    const float* w    = reinterpret_cast<const float*>(d_in[1]);
    const float* bias = reinterpret_cast<const float*>(d_in[2]);
    float* out = reinterpret_cast<float*>(d_out);

    const int n4 = MTOT * KTOT / 4;
    prep_x_kernel<<<(n4 + 255) / 256, 256>>>(reinterpret_cast<const float4*>(x));
    prep_w_kernel<<<(n4 + 255) / 256, 256>>>(reinterpret_cast<const float4*>(w));

    cudaFuncSetAttribute(bgemm_kernel,
                         cudaFuncAttributeMaxDynamicSharedMemorySize, SMEM_TOTAL);
    dim3 grid(NTOT / BN, MTOT / BM);   // (16, 32)
    bgemm_kernel<<<grid, THREADS, SMEM_TOTAL>>>(bias, out);
}